// round 1
// baseline (speedup 1.0000x reference)
#include <cuda_runtime.h>
#include <cuda_bf16.h>

// Problem constants
#define HIDDEN   64
#define SEQ_LEN  128
#define BATCH    64
#define NPTS     (BATCH * SEQ_LEN)   // 8192
#define T_MAX_V  20.0f
#define KTERMS   40                  // moment expansion order

// ---------------- device scratch (no allocations allowed) ----------------
__device__ float  g_lt[NPTS];        // learner times [B*S]
__device__ float  g_lc[NPTS];        // compacted valid learner times
__device__ int    g_nl;              // count of valid learner times
__device__ double g_Me[KTERMS];      // expert moments  sum m*e^{-t^2} t^k
__device__ double g_Ml[KTERMS];      // learner moments (t<8 window)
__device__ double g_ll;              // brute-force ll sum

// ---------------- init ----------------
__global__ void pp_init_kernel() {
    g_nl = 0;
    g_ll = 0.0;
}

// ---------------- rollout: 64 blocks (one per batch), 256 threads ----------------
__global__ void __launch_bounds__(256, 1)
pp_rollout_kernel(const float* __restrict__ pool,
                  const float* __restrict__ Wih,
                  const float* __restrict__ Whh,
                  const float* __restrict__ bih,
                  const float* __restrict__ bhh,
                  const float* __restrict__ Vw,
                  const float* __restrict__ Vb) {
    const int b = blockIdx.x;
    const int r = threadIdx.x;     // gate row 0..255 (i,f,g,o blocks of 64)

    __shared__ float hx_s[HIDDEN];
    __shared__ float red_s[HIDDEN];
    __shared__ float gate_s[4 * HIDDEN];
    __shared__ float cum_s;

    // cache this thread's W_hh row in registers
    float w[HIDDEN];
#pragma unroll
    for (int j = 0; j < HIDDEN; j++) w[j] = Whh[r * HIDDEN + j];
    const float wih  = Wih[r];
    const float bias = bih[r] + bhh[r];
    const float vb   = Vb[0];
    float vw_r = 0.f;
    if (r < HIDDEN) vw_r = Vw[r];

    float cx = 0.f;                // thread r<64 owns cell state r
    if (r < HIDDEN) { hx_s[r] = 0.f; red_s[r] = 0.f; }
    if (r == 0) cum_s = 0.f;
    __syncthreads();

    for (int s = 0; s < SEQ_LEN; s++) {
        // ---- sigma from OLD hx (red_s = hx*Vw precomputed), cum update ----
        if (r < 32) {
            float x = red_s[r] + red_s[r + 32];
#pragma unroll
            for (int o = 16; o > 0; o >>= 1) x += __shfl_xor_sync(0xffffffffu, x, o);
            if (r == 0) {
                float z = x + vb;
                float sigma = (z > 0.f ? z : (expf(z) - 1.f)) + 1.f;   // elu + 1
                float u = pool[b * SEQ_LEN + s];
                float c = cum_s + (-logf(u)) / sigma;
                cum_s = c;
                g_lt[b * SEQ_LEN + s] = c;
            }
        }
        __syncthreads();

        // ---- gates = cum*Wih + bias + Whh@hx ----
        float g = fmaf(cum_s, wih, bias);
        const float4* h4 = (const float4*)hx_s;
#pragma unroll
        for (int j4 = 0; j4 < HIDDEN / 4; j4++) {
            float4 h = h4[j4];
            g = fmaf(w[4 * j4 + 0], h.x, g);
            g = fmaf(w[4 * j4 + 1], h.y, g);
            g = fmaf(w[4 * j4 + 2], h.z, g);
            g = fmaf(w[4 * j4 + 3], h.w, g);
        }
        gate_s[r] = g;
        __syncthreads();

        // ---- LSTM state update (threads 0..63) ----
        if (r < HIDDEN) {
            float ig = 1.f / (1.f + __expf(-gate_s[r]));
            float fg = 1.f / (1.f + __expf(-gate_s[r + HIDDEN]));
            float gg = tanhf(gate_s[r + 2 * HIDDEN]);
            float og = 1.f / (1.f + __expf(-gate_s[r + 3 * HIDDEN]));
            cx = fg * cx + ig * gg;
            float h = og * tanhf(cx);
            hx_s[r]  = h;
            red_s[r] = h * vw_r;   // pre-stage next step's sigma dot
        }
        __syncthreads();
    }
}

// ---------------- moments + compaction: 2 blocks x 512 threads ----------------
// block 0: expert moments.  block 1: learner moments + compaction of valid times.
__global__ void __launch_bounds__(512, 1)
pp_moments_kernel(const float* __restrict__ et) {
    const int  tid = threadIdx.x;
    const bool isE = (blockIdx.x == 0);

    float acc[KTERMS];
#pragma unroll
    for (int k = 0; k < KTERMS; k++) acc[k] = 0.f;

    for (int p = tid; p < NPTS; p += 512) {
        float t = isE ? et[p] : g_lt[p];
        bool valid = (t > 0.f) && (t < T_MAX_V);
        if (!isE && valid) {
            int idx = atomicAdd(&g_nl, 1);
            g_lc[idx] = t;
        }
        // learner moments only matter within reach of experts (t_e<=1);
        // t>=8 contributes < e^{-49} per pair -> drop (also avoids t^k overflow)
        float wgt = (valid && t < 8.f) ? __expf(-t * t) : 0.f;
        float wp = wgt;
#pragma unroll
        for (int k = 0; k < KTERMS; k++) { acc[k] += wp; wp *= t; }
    }

    // warp reduce then cross-warp reduce
    __shared__ float wsum[16][KTERMS];
    const int wrp = tid >> 5, lane = tid & 31;
#pragma unroll
    for (int k = 0; k < KTERMS; k++) {
        float v = acc[k];
#pragma unroll
        for (int o = 16; o > 0; o >>= 1) v += __shfl_xor_sync(0xffffffffu, v, o);
        if (lane == 0) wsum[wrp][k] = v;
    }
    __syncthreads();
    if (tid < KTERMS) {
        double s = 0.0;
#pragma unroll
        for (int ww = 0; ww < 16; ww++) s += (double)wsum[ww][tid];
        if (isE) g_Me[tid] = s; else g_Ml[tid] = s;
    }
}

// ---------------- ll brute force over compacted learner points ----------------
__global__ void __launch_bounds__(128, 8)
pp_ll_kernel() {
    const int T = gridDim.x * blockDim.x;
    const int g = blockIdx.x * blockDim.x + threadIdx.x;
    const int nl = g_nl;

    float acc = 0.f;
    if (nl > 0) {
        const int R = T / nl;           // replicas per i (T=65536 >= nl)
        if (g < R * nl) {
            const int i  = g % nl;
            const int r0 = g / nl;
            const float ti = g_lc[i];
            for (int j = r0; j < nl; j += R) {
                float d = ti - g_lc[j];
                acc += __expf(-d * d);
            }
        }
    }

    // block reduce -> one double atomic per block
    __shared__ float bsum[4];
#pragma unroll
    for (int o = 16; o > 0; o >>= 1) acc += __shfl_xor_sync(0xffffffffu, acc, o);
    const int wrp = threadIdx.x >> 5, lane = threadIdx.x & 31;
    if (lane == 0) bsum[wrp] = acc;
    __syncthreads();
    if (threadIdx.x == 0) {
        double s = (double)bsum[0] + (double)bsum[1] + (double)bsum[2] + (double)bsum[3];
        atomicAdd(&g_ll, s);
    }
}

// ---------------- finalize: ee + ll - 2*le via moment expansion ----------------
__global__ void pp_finalize_kernel(float* __restrict__ out) {
    double ee = 0.0, le = 0.0, c = 1.0;   // c_k = 2^k / k!
    for (int k = 0; k < KTERMS; k++) {
        if (k > 0) c *= 2.0 / (double)k;
        double me = g_Me[k];
        ee += c * me * me;
        le += c * me * g_Ml[k];
    }
    out[0] = (float)(ee + g_ll - 2.0 * le);
}

// ---------------- launch ----------------
extern "C" void kernel_launch(void* const* d_in, const int* in_sizes, int n_in,
                              void* d_out, int out_size) {
    const float* pool = (const float*)d_in[0];   // rand_uniform_pool [64,128]
    const float* et   = (const float*)d_in[1];   // expert_time       [64,128]
    const float* Wih  = (const float*)d_in[2];   // [256,1]
    const float* Whh  = (const float*)d_in[3];   // [256,64]
    const float* bih  = (const float*)d_in[4];   // [256]
    const float* bhh  = (const float*)d_in[5];   // [256]
    const float* Vw   = (const float*)d_in[6];   // [1,64]
    const float* Vb   = (const float*)d_in[7];   // [1]
    float* out = (float*)d_out;

    pp_init_kernel<<<1, 1>>>();
    pp_rollout_kernel<<<BATCH, 256>>>(pool, Wih, Whh, bih, bhh, Vw, Vb);
    pp_moments_kernel<<<2, 512>>>(et);
    pp_ll_kernel<<<512, 128>>>();
    pp_finalize_kernel<<<1, 1>>>(out);
}

// round 2
// speedup vs baseline: 1.6067x; 1.6067x over previous
#include <cuda_runtime.h>
#include <cuda_bf16.h>

#define HIDDEN   64
#define SEQ_LEN  128
#define BATCH    64
#define NPTS     (BATCH * SEQ_LEN)   // 8192
#define T_MAX_V  20.0f
#define KTERMS   40

// ---------------- device scratch ----------------
__device__ float  g_lt[NPTS];
__device__ float  g_lc[NPTS];
__device__ int    g_nl;
__device__ double g_Me[KTERMS];
__device__ double g_Ml[KTERMS];
__device__ double g_ll;

// ---------------- f32x2 helpers ----------------
__device__ __forceinline__ unsigned long long pk2(float lo, float hi) {
    unsigned long long u;
    asm("mov.b64 %0, {%1, %2};" : "=l"(u) : "f"(lo), "f"(hi));
    return u;
}
__device__ __forceinline__ void upk2(unsigned long long u, float& lo, float& hi) {
    asm("mov.b64 {%0, %1}, %2;" : "=f"(lo), "=f"(hi) : "l"(u));
}
#define FFMA2(acc, a, b) \
    asm("fma.rn.f32x2 %0, %1, %2, %0;" : "+l"(acc) : "l"(a), "l"(b))

__device__ __forceinline__ float fast_sigmoid(float x) {
    return __fdividef(1.f, 1.f + __expf(-x));
}
__device__ __forceinline__ float fast_tanh(float x) {
    return __fdividef(2.f, 1.f + __expf(-2.f * x)) - 1.f;
}

// ---------------- rollout: 64 blocks x 256 threads ----------------
__global__ void __launch_bounds__(256, 1)
pp_rollout_kernel(const float* __restrict__ pool,
                  const float* __restrict__ Wih,
                  const float* __restrict__ Whh,
                  const float* __restrict__ bih,
                  const float* __restrict__ bhh,
                  const float* __restrict__ Vw,
                  const float* __restrict__ Vb) {
    const int b = blockIdx.x;
    const int r = threadIdx.x;          // gate row 0..255 (i,f,g,o blocks of 64)

    __shared__ __align__(16) float hx_s[HIDDEN];
    __shared__ float m_s[4 * HIDDEN];
    __shared__ float p_s[2];            // hv warp partials
    __shared__ float cum_s;
    __shared__ float lg_s[SEQ_LEN];     // -log(u) per step
    __shared__ float cum_hist[SEQ_LEN];

    // fuse global init (rollout completes before moments kernel, stream order)
    if (b == 0 && r == 255) { g_nl = 0; g_ll = 0.0; }

    // preload W_hh row as packed f32x2 pairs
    unsigned long long w2[32];
    {
        const float4* wrow = (const float4*)(Whh + r * HIDDEN);
#pragma unroll
        for (int q = 0; q < 16; q++) {
            float4 v = wrow[q];
            w2[2 * q]     = pk2(v.x, v.y);
            w2[2 * q + 1] = pk2(v.z, v.w);
        }
    }
    const float bias = bih[r] + bhh[r];
    const float vb   = Vb[0];

    // update-thread preloads
    float wih_i = 0.f, wih_f = 0.f, wih_g = 0.f, wih_o = 0.f, vw_r = 0.f;
    if (r < HIDDEN) {
        wih_i = Wih[r];
        wih_f = Wih[r + HIDDEN];
        wih_g = Wih[r + 2 * HIDDEN];
        wih_o = Wih[r + 3 * HIDDEN];
        vw_r  = Vw[r];
        hx_s[r] = 0.f;
    }
    if (r < 2)   p_s[r] = 0.f;
    if (r < SEQ_LEN) lg_s[r] = -__logf(pool[b * SEQ_LEN + r]);

    float cx    = 0.f;   // cell state (threads r<64)
    float cum_v = 0.f;   // thread 0 only
    __syncthreads();

    for (int s = 0; s < SEQ_LEN; s++) {
        // ---- phase A: cum chain (thread 0) || matvec m = bias + Whh@hx (all) ----
        if (r == 0) {
            float S = p_s[0] + p_s[1];
            float z = S + vb;
            float sigma = (z > 0.f ? z : (__expf(z) - 1.f)) + 1.f;   // elu + 1
            cum_v += __fdividef(lg_s[s], sigma);
            cum_s = cum_v;
            cum_hist[s] = cum_v;
        }
        {
            unsigned long long acc0 = pk2(bias, 0.f);
            unsigned long long acc1 = 0ull, acc2 = 0ull, acc3 = 0ull;
            const ulonglong2* h4 = (const ulonglong2*)hx_s;
#pragma unroll
            for (int j = 0; j < 8; j++) {
                ulonglong2 ha = h4[2 * j];
                ulonglong2 hb = h4[2 * j + 1];
                FFMA2(acc0, w2[4 * j + 0], ha.x);
                FFMA2(acc1, w2[4 * j + 1], ha.y);
                FFMA2(acc2, w2[4 * j + 2], hb.x);
                FFMA2(acc3, w2[4 * j + 3], hb.y);
            }
            float a0, a1, b0, b1, c0, c1, d0, d1;
            upk2(acc0, a0, a1); upk2(acc1, b0, b1);
            upk2(acc2, c0, c1); upk2(acc3, d0, d1);
            m_s[r] = ((a0 + a1) + (b0 + b1)) + ((c0 + c1) + (d0 + d1));
        }
        __syncthreads();

        // ---- phase B: LSTM update (threads 0..63) ----
        if (r < HIDDEN) {
            float cum = cum_s;
            float gi = fmaf(cum, wih_i, m_s[r]);
            float gf = fmaf(cum, wih_f, m_s[r + HIDDEN]);
            float gg = fmaf(cum, wih_g, m_s[r + 2 * HIDDEN]);
            float go = fmaf(cum, wih_o, m_s[r + 3 * HIDDEN]);
            float ig = fast_sigmoid(gi);
            float fg = fast_sigmoid(gf);
            float gt = fast_tanh(gg);
            float og = fast_sigmoid(go);
            cx = fmaf(fg, cx, ig * gt);
            float h = og * fast_tanh(cx);
            hx_s[r] = h;
            // hv reduction within each of the two warps
            float hv = h * vw_r;
#pragma unroll
            for (int o = 16; o > 0; o >>= 1)
                hv += __shfl_xor_sync(0xffffffffu, hv, o);
            if ((r & 31) == 0) p_s[r >> 5] = hv;
        }
        __syncthreads();
    }

    // dump learner times
    if (r < SEQ_LEN) g_lt[b * SEQ_LEN + r] = cum_hist[r];
}

// ---------------- moments + compaction: 2 blocks x 512 threads ----------------
__global__ void __launch_bounds__(512, 1)
pp_moments_kernel(const float* __restrict__ et) {
    const int  tid = threadIdx.x;
    const bool isE = (blockIdx.x == 0);

    float acc[KTERMS];
#pragma unroll
    for (int k = 0; k < KTERMS; k++) acc[k] = 0.f;

    for (int p = tid; p < NPTS; p += 512) {
        float t = isE ? et[p] : g_lt[p];
        bool valid = (t > 0.f) && (t < T_MAX_V);
        if (!isE && valid) {
            int idx = atomicAdd(&g_nl, 1);
            g_lc[idx] = t;
        }
        float wgt = (valid && t < 8.f) ? __expf(-t * t) : 0.f;
        float wp = wgt;
#pragma unroll
        for (int k = 0; k < KTERMS; k++) { acc[k] += wp; wp *= t; }
    }

    __shared__ float wsum[16][KTERMS];
    const int wrp = tid >> 5, lane = tid & 31;
#pragma unroll
    for (int k = 0; k < KTERMS; k++) {
        float v = acc[k];
#pragma unroll
        for (int o = 16; o > 0; o >>= 1) v += __shfl_xor_sync(0xffffffffu, v, o);
        if (lane == 0) wsum[wrp][k] = v;
    }
    __syncthreads();
    if (tid < KTERMS) {
        double s = 0.0;
#pragma unroll
        for (int ww = 0; ww < 16; ww++) s += (double)wsum[ww][tid];
        if (isE) g_Me[tid] = s; else g_Ml[tid] = s;
    }
}

// ---------------- ll brute force over compacted learner points ----------------
__global__ void __launch_bounds__(128, 8)
pp_ll_kernel() {
    const int T = gridDim.x * blockDim.x;
    const int g = blockIdx.x * blockDim.x + threadIdx.x;
    const int nl = g_nl;

    float acc = 0.f;
    if (nl > 0) {
        const int R = T / nl;
        if (g < R * nl) {
            const int i  = g % nl;
            const int r0 = g / nl;
            const float ti = g_lc[i];
            for (int j = r0; j < nl; j += R) {
                float d = ti - g_lc[j];
                acc += __expf(-d * d);
            }
        }
    }

    __shared__ float bsum[4];
#pragma unroll
    for (int o = 16; o > 0; o >>= 1) acc += __shfl_xor_sync(0xffffffffu, acc, o);
    const int wrp = threadIdx.x >> 5, lane = threadIdx.x & 31;
    if (lane == 0) bsum[wrp] = acc;
    __syncthreads();
    if (threadIdx.x == 0) {
        double s = (double)bsum[0] + (double)bsum[1] + (double)bsum[2] + (double)bsum[3];
        atomicAdd(&g_ll, s);
    }
}

// ---------------- finalize ----------------
__global__ void pp_finalize_kernel(float* __restrict__ out) {
    double ee = 0.0, le = 0.0, c = 1.0;   // c_k = 2^k / k!
    for (int k = 0; k < KTERMS; k++) {
        if (k > 0) c *= 2.0 / (double)k;
        double me = g_Me[k];
        ee += c * me * me;
        le += c * me * g_Ml[k];
    }
    out[0] = (float)(ee + g_ll - 2.0 * le);
}

// ---------------- launch ----------------
extern "C" void kernel_launch(void* const* d_in, const int* in_sizes, int n_in,
                              void* d_out, int out_size) {
    const float* pool = (const float*)d_in[0];
    const float* et   = (const float*)d_in[1];
    const float* Wih  = (const float*)d_in[2];
    const float* Whh  = (const float*)d_in[3];
    const float* bih  = (const float*)d_in[4];
    const float* bhh  = (const float*)d_in[5];
    const float* Vw   = (const float*)d_in[6];
    const float* Vb   = (const float*)d_in[7];
    float* out = (float*)d_out;

    pp_rollout_kernel<<<BATCH, 256>>>(pool, Wih, Whh, bih, bhh, Vw, Vb);
    pp_moments_kernel<<<2, 512>>>(et);
    pp_ll_kernel<<<512, 128>>>();
    pp_finalize_kernel<<<1, 1>>>(out);
}

// round 5
// speedup vs baseline: 1.6946x; 1.0548x over previous
#include <cuda_runtime.h>
#include <cuda_bf16.h>

#define HIDDEN   64
#define SEQ_LEN  128
#define BATCH    64
#define NPTS     (BATCH * SEQ_LEN)   // 8192
#define T_MAX_V  20.0f
#define KTERMS   40

// ---------------- device scratch ----------------
__device__ float  g_lt[NPTS];
__device__ float  g_lc[NPTS];
__device__ int    g_nl;
__device__ int    g_done;
__device__ double g_Me[KTERMS];
__device__ double g_Ml[KTERMS];
__device__ double g_ll;

// c_k = 2^k / k!
__constant__ double c_coef[KTERMS] = {
    1.0, 2.0, 2.0, 1.3333333333333333, 0.6666666666666666,
    0.26666666666666666, 0.08888888888888889, 0.025396825396825397,
    0.006349206349206349, 0.0014109347442680775, 2.821869488536155e-04,
    5.130671797338464e-05, 8.551119662230773e-06, 1.3155568711124266e-06,
    1.8793669587320378e-07, 2.505822611642717e-08, 3.132278264553396e-09,
    3.6850332524157603e-10, 4.0944813915730673e-11, 4.3099804121822816e-12,
    4.3099804121822815e-13, 4.104743249697411e-14, 3.7315847724521917e-15,
    3.244856323871471e-16, 2.7040469365595593e-17, 2.1632375492476474e-18,
    1.6640288840366519e-19, 1.2326139881753718e-20, 8.804385629824085e-22,
    6.072024572292472e-23, 4.048016381528315e-24, 2.6116234719537516e-25,
    1.6322646699710948e-26, 9.892513151339969e-28, 5.819125383141158e-29,
    3.325214504652090e-30, 1.847341391473383e-31, 9.985629143099369e-33,
    5.255594285841772e-34, 2.695176556841934e-35
};

// ---------------- helpers ----------------
__device__ __forceinline__ unsigned long long pk2(float lo, float hi) {
    unsigned long long u;
    asm("mov.b64 %0, {%1, %2};" : "=l"(u) : "f"(lo), "f"(hi));
    return u;
}
__device__ __forceinline__ void upk2(unsigned long long u, float& lo, float& hi) {
    asm("mov.b64 {%0, %1}, %2;" : "=f"(lo), "=f"(hi) : "l"(u));
}
#define FFMA2(acc, a, b) \
    asm("fma.rn.f32x2 %0, %1, %2, %0;" : "+l"(acc) : "l"(a), "l"(b))

__device__ __forceinline__ float tanh_apx(float x) {
    float y;
    asm("tanh.approx.f32 %0, %1;" : "=f"(y) : "f"(x));
    return y;
}
__device__ __forceinline__ float sigm_apx(float x) {
    return fmaf(tanh_apx(0.5f * x), 0.5f, 0.5f);
}

#define BAR_SYNC(id, cnt)   asm volatile("bar.sync %0, %1;"   :: "r"(id), "r"(cnt) : "memory")
#define BAR_ARRIVE(id, cnt) asm volatile("bar.arrive %0, %1;" :: "r"(id), "r"(cnt) : "memory")

// ================= kernel 1: init + expert moments (1 block x 1024) =================
__global__ void __launch_bounds__(1024, 1)
pp_init_expert(const float* __restrict__ et) {
    const int tid = threadIdx.x;
    if (tid == 0) { g_nl = 0; g_done = 0; g_ll = 0.0; }
    if (tid < KTERMS) g_Ml[tid] = 0.0;

    float acc[KTERMS];
#pragma unroll
    for (int k = 0; k < KTERMS; k++) acc[k] = 0.f;

    for (int p = tid; p < NPTS; p += 1024) {
        float t = et[p];
        bool valid = (t > 0.f) && (t < T_MAX_V);
        float wp = valid ? __expf(-t * t) : 0.f;
#pragma unroll
        for (int k = 0; k < KTERMS; k++) { acc[k] += wp; wp *= t; }
    }

    __shared__ float wsum[32][KTERMS];
    const int wrp = tid >> 5, lane = tid & 31;
#pragma unroll
    for (int k = 0; k < KTERMS; k++) {
        float v = acc[k];
#pragma unroll
        for (int o = 16; o > 0; o >>= 1) v += __shfl_xor_sync(0xffffffffu, v, o);
        if (lane == 0) wsum[wrp][k] = v;
    }
    __syncthreads();
    if (tid < KTERMS) {
        double s = 0.0;
#pragma unroll
        for (int ww = 0; ww < 32; ww++) s += (double)wsum[ww][tid];
        g_Me[tid] = s;
    }
}

// ================= kernel 2: rollout (64 blocks x 288) =================
// W0: matvec rows 0-31 + LSTM update (2 units/lane)
// W1-7: matvec rows 32-255
// W8: sigma/cum chain (shuffle reduce overlapped with matvec)
__global__ void __launch_bounds__(288, 1)
pp_rollout_kernel(const float* __restrict__ pool,
                  const float* __restrict__ Wih,
                  const float* __restrict__ Whh,
                  const float* __restrict__ bih,
                  const float* __restrict__ bhh,
                  const float* __restrict__ Vw,
                  const float* __restrict__ Vb) {
    const int b    = blockIdx.x;
    const int tid  = threadIdx.x;
    const int wid  = tid >> 5;
    const int lane = tid & 31;

    __shared__ __align__(16) float hx_s[HIDDEN];
    __shared__ __align__(16) float m_s[4 * HIDDEN];
    __shared__ __align__(16) float pow_s[KTERMS][SEQ_LEN];   // 20KB, epilogue only
    __shared__ __align__(16) float lg_s[SEQ_LEN];
    __shared__ __align__(16) float cum_hist[SEQ_LEN];
    __shared__ float red_s[32];
    __shared__ float cum_s;

    // matvec weight preload (rows 0..255)
    unsigned long long w2[32];
    float bias = 0.f;
    if (tid < 256) {
        const float4* wrow = (const float4*)(Whh + tid * HIDDEN);
#pragma unroll
        for (int q = 0; q < 16; q++) {
            float4 v = wrow[q];
            w2[2 * q]     = pk2(v.x, v.y);
            w2[2 * q + 1] = pk2(v.z, v.w);
        }
        bias = bih[tid] + bhh[tid];
    }
    const float vb = Vb[0];

    // update-warp preload (W0: units lane and lane+32)
    float wi1 = 0, wf1 = 0, wg1 = 0, wo1 = 0, vw1 = 0;
    float wi2 = 0, wf2 = 0, wg2 = 0, wo2 = 0, vw2 = 0;
    if (wid == 0) {
        wi1 = Wih[lane];            wi2 = Wih[lane + 32];
        wf1 = Wih[lane + 64];       wf2 = Wih[lane + 96];
        wg1 = Wih[lane + 128];      wg2 = Wih[lane + 160];
        wo1 = Wih[lane + 192];      wo2 = Wih[lane + 224];
        vw1 = Vw[lane];             vw2 = Vw[lane + 32];
    }
    if (tid < HIDDEN) hx_s[tid] = 0.f;
    if (tid < 32)     red_s[tid] = 0.f;
    if (tid < SEQ_LEN) lg_s[tid] = -__logf(pool[b * SEQ_LEN + tid]);

    float cx1 = 0.f, cx2 = 0.f;   // W0 cell states
    float cum_v = 0.f;            // W8 lane 0
    __syncthreads();

    for (int s = 0; s < SEQ_LEN; s++) {
        // ---------------- phase A ----------------
        if (wid < 8) {
            // matvec row tid: m = bias + Whh[tid,:] @ hx
            unsigned long long acc0 = pk2(bias, 0.f);
            unsigned long long acc1 = 0ull, acc2 = 0ull, acc3 = 0ull;
            const ulonglong2* h4 = (const ulonglong2*)hx_s;
#pragma unroll
            for (int j = 0; j < 8; j++) {
                ulonglong2 ha = h4[2 * j];
                ulonglong2 hb = h4[2 * j + 1];
                FFMA2(acc0, w2[4 * j + 0], ha.x);
                FFMA2(acc1, w2[4 * j + 1], ha.y);
                FFMA2(acc2, w2[4 * j + 2], hb.x);
                FFMA2(acc3, w2[4 * j + 3], hb.y);
            }
            float a0, a1, b0, b1, c0, c1, d0, d1;
            upk2(acc0, a0, a1); upk2(acc1, b0, b1);
            upk2(acc2, c0, c1); upk2(acc3, d0, d1);
            m_s[tid] = ((a0 + a1) + (b0 + b1)) + ((c0 + c1) + (d0 + d1));
        } else {
            // sigma/cum chain from red_s (written by W0 last step)
            float x = red_s[lane];
#pragma unroll
            for (int o = 16; o > 0; o >>= 1) x += __shfl_xor_sync(0xffffffffu, x, o);
            if (lane == 0) {
                float z = x + vb;
                float sigma = (z > 0.f ? z : (__expf(z) - 1.f)) + 1.f;   // elu + 1
                cum_v += __fdividef(lg_s[s], sigma);
                cum_s = cum_v;
                cum_hist[s] = cum_v;
            }
        }

        // ---------------- phase B ----------------
        if (wid == 0) {
            BAR_SYNC(1, 288);        // wait: all m_s + cum_s ready
            const float cum = cum_s;
            float mi1 = m_s[lane],       mi2 = m_s[lane + 32];
            float mf1 = m_s[lane + 64],  mf2 = m_s[lane + 96];
            float mg1 = m_s[lane + 128], mg2 = m_s[lane + 160];
            float mo1 = m_s[lane + 192], mo2 = m_s[lane + 224];

            float ig1 = sigm_apx(fmaf(cum, wi1, mi1));
            float fg1 = sigm_apx(fmaf(cum, wf1, mf1));
            float gt1 = tanh_apx(fmaf(cum, wg1, mg1));
            float og1 = sigm_apx(fmaf(cum, wo1, mo1));
            cx1 = fmaf(fg1, cx1, ig1 * gt1);
            float h1 = og1 * tanh_apx(cx1);

            float ig2 = sigm_apx(fmaf(cum, wi2, mi2));
            float fg2 = sigm_apx(fmaf(cum, wf2, mf2));
            float gt2 = tanh_apx(fmaf(cum, wg2, mg2));
            float og2 = sigm_apx(fmaf(cum, wo2, mo2));
            cx2 = fmaf(fg2, cx2, ig2 * gt2);
            float h2 = og2 * tanh_apx(cx2);

            hx_s[lane]      = h1;
            hx_s[lane + 32] = h2;
            red_s[lane] = fmaf(h1, vw1, h2 * vw2);
            __syncwarp();
            BAR_ARRIVE(2, 288);      // release matvec + sigma warps
        } else {
            BAR_ARRIVE(1, 288);
            BAR_SYNC(2, 288);        // wait: hx_s / red_s updated
        }
    }
    __syncthreads();

    // ---------------- epilogue: g_lt + learner moments + compaction ----------------
    if (tid < SEQ_LEN) {
        float t = cum_hist[tid];
        g_lt[b * SEQ_LEN + tid] = t;
        bool valid = (t > 0.f) && (t < T_MAX_V);
        float wp = (valid && t < 8.f) ? __expf(-t * t) : 0.f;
#pragma unroll
        for (int k = 0; k < KTERMS; k++) { pow_s[k][tid] = wp; wp *= t; }

        unsigned bal = __ballot_sync(0xffffffffu, valid);
        int base = 0;
        if (lane == 0) base = atomicAdd(&g_nl, __popc(bal));
        base = __shfl_sync(0xffffffffu, base, 0);
        if (valid) g_lc[base + __popc(bal & ((1u << lane) - 1u))] = t;
    }
    __syncthreads();
    if (tid < KTERMS) {
        const float4* row = (const float4*)pow_s[tid];
        float s0 = 0.f, s1 = 0.f, s2 = 0.f, s3 = 0.f;
#pragma unroll
        for (int q = 0; q < SEQ_LEN / 4; q++) {
            float4 v = row[q];
            s0 += v.x; s1 += v.y; s2 += v.z; s3 += v.w;
        }
        atomicAdd(&g_Ml[tid], (double)((s0 + s1) + (s2 + s3)));
    }
}

// ================= kernel 3: ll (symmetric) + fused finalize =================
__global__ void __launch_bounds__(128, 8)
pp_ll_fin_kernel(float* __restrict__ out) {
    const int T = gridDim.x * blockDim.x;
    const int g = blockIdx.x * blockDim.x + threadIdx.x;
    const int nl = g_nl;

    float acc = 0.f;
    if (nl > 0) {
        const int R = T / nl;
        if (g < R * nl) {
            const int i  = g % nl;
            const int r0 = g / nl;
            const float ti = g_lc[i];
            for (int j = i + 1 + r0; j < nl; j += R) {
                float d = ti - g_lc[j];
                acc += __expf(-d * d);
            }
        }
    }

    __shared__ float bsum[4];
#pragma unroll
    for (int o = 16; o > 0; o >>= 1) acc += __shfl_xor_sync(0xffffffffu, acc, o);
    const int wrp = threadIdx.x >> 5, lane = threadIdx.x & 31;
    if (lane == 0) bsum[wrp] = acc;
    __syncthreads();
    if (threadIdx.x == 0) {
        double s = (double)bsum[0] + (double)bsum[1] + (double)bsum[2] + (double)bsum[3];
        atomicAdd(&g_ll, s);
    }

    // last-block finalize
    __threadfence();
    __shared__ int is_last;
    if (threadIdx.x == 0)
        is_last = (atomicAdd(&g_done, 1) == (int)gridDim.x - 1);
    __syncthreads();
    if (is_last) {
        __shared__ double t_ee[KTERMS], t_le[KTERMS];
        if (threadIdx.x < KTERMS) {
            double c  = c_coef[threadIdx.x];
            double me = g_Me[threadIdx.x];
            t_ee[threadIdx.x] = c * me * me;
            t_le[threadIdx.x] = c * me * g_Ml[threadIdx.x];
        }
        __syncthreads();
        if (threadIdx.x == 0) {
            double e0 = 0, e1 = 0, e2 = 0, e3 = 0, l0 = 0, l1 = 0, l2 = 0, l3 = 0;
#pragma unroll
            for (int k = 0; k < KTERMS; k += 4) {
                e0 += t_ee[k]; e1 += t_ee[k + 1]; e2 += t_ee[k + 2]; e3 += t_ee[k + 3];
                l0 += t_le[k]; l1 += t_le[k + 1]; l2 += t_le[k + 2]; l3 += t_le[k + 3];
            }
            double ee = (e0 + e1) + (e2 + e3);
            double le = (l0 + l1) + (l2 + l3);
            double ll = 2.0 * g_ll + (double)g_nl;   // symmetry: off-diag*2 + diagonal
            out[0] = (float)(ee + ll - 2.0 * le);
        }
    }
}

// ---------------- launch ----------------
extern "C" void kernel_launch(void* const* d_in, const int* in_sizes, int n_in,
                              void* d_out, int out_size) {
    const float* pool = (const float*)d_in[0];
    const float* et   = (const float*)d_in[1];
    const float* Wih  = (const float*)d_in[2];
    const float* Whh  = (const float*)d_in[3];
    const float* bih  = (const float*)d_in[4];
    const float* bhh  = (const float*)d_in[5];
    const float* Vw   = (const float*)d_in[6];
    const float* Vb   = (const float*)d_in[7];
    float* out = (float*)d_out;

    pp_init_expert<<<1, 1024>>>(et);
    pp_rollout_kernel<<<BATCH, 288>>>(pool, Wih, Whh, bih, bhh, Vw, Vb);
    pp_ll_fin_kernel<<<512, 128>>>(out);
}